// round 5
// baseline (speedup 1.0000x reference)
#include <cuda_runtime.h>
#include <math.h>

#define HID 1024
#define EMB 1024
#define MAXLEN 4096
#define VOCAB 50257
#define NPART 32          // ctx partial slices (t-chunks)
#define K5_BLOCKS ((VOCAB + 7) / 8)

// ---------------- device scratch ----------------
__device__ float g_hnew[HID];
__device__ float g_scores[MAXLEN];
__device__ float g_ctx_part[NPART * HID];
__device__ float g_hid[HID];
__device__ float g_lse_m[K5_BLOCKS];
__device__ float g_lse_l[K5_BLOCKS];
__device__ float g_lse;

__device__ __forceinline__ float warp_sum(float v) {
#pragma unroll
    for (int o = 16; o; o >>= 1) v += __shfl_down_sync(0xffffffffu, v, o);
    return v;
}
__device__ __forceinline__ float warp_max(float v) {
#pragma unroll
    for (int o = 16; o; o >>= 1) v = fmaxf(v, __shfl_down_sync(0xffffffffu, v, o));
    return v;
}

__device__ __forceinline__ float sigmoidf(float x) { return 1.f / (1.f + expf(-x)); }

// ---------------- K1: gates GEMV + LSTM pointwise ----------------
__global__ void k1_lstm(const float* __restrict__ W_ih, const float* __restrict__ W_hh,
                        const float* __restrict__ b_ih, const float* __restrict__ b_hh,
                        const float* __restrict__ x, const float* __restrict__ h,
                        const float* __restrict__ c, float* __restrict__ out_tail) {
    __shared__ __align__(16) float sx[EMB];
    __shared__ __align__(16) float sh[HID];
    for (int k = threadIdx.x; k < EMB; k += blockDim.x) sx[k] = x[k];
    for (int k = threadIdx.x; k < HID; k += blockDim.x) sh[k] = h[k];
    __syncthreads();

    int j = (blockIdx.x * blockDim.x + threadIdx.x) >> 5;
    int lane = threadIdx.x & 31;
    if (j >= HID) return;

    const float4* x4 = (const float4*)sx;
    const float4* h4 = (const float4*)sh;
    float acc[4];
#pragma unroll
    for (int g = 0; g < 4; g++) {
        const float4* rW = (const float4*)(W_ih + (size_t)(g * HID + j) * EMB);
        const float4* rU = (const float4*)(W_hh + (size_t)(g * HID + j) * HID);
        float a = 0.f;
#pragma unroll
        for (int k = lane; k < EMB / 4; k += 32) {
            float4 w = rW[k], xv = x4[k];
            a += w.x * xv.x + w.y * xv.y + w.z * xv.z + w.w * xv.w;
            float4 u = rU[k], hv = h4[k];
            a += u.x * hv.x + u.y * hv.y + u.z * hv.z + u.w * hv.w;
        }
        acc[g] = warp_sum(a);
    }
    if (lane == 0) {
        float gi = acc[0] + b_ih[j]           + b_hh[j];
        float gf = acc[1] + b_ih[HID + j]     + b_hh[HID + j];
        float gg = acc[2] + b_ih[2 * HID + j] + b_hh[2 * HID + j];
        float go = acc[3] + b_ih[3 * HID + j] + b_hh[3 * HID + j];
        float ig = sigmoidf(gi);
        float fg = sigmoidf(gf);
        float gt = tanhf(gg);
        float og = sigmoidf(go);
        float cn = fg * c[j] + ig * gt;
        float hn = og * tanhf(cn);
        g_hnew[j] = hn;
        out_tail[j] = hn;          // h_new
        out_tail[HID + j] = cn;    // c_new
    }
}

// ---------------- K2: scores[t] = dot(A[t,:], h_new) ----------------
__global__ void k2_scores(const float* __restrict__ A) {
    __shared__ __align__(16) float sh[HID];
    for (int k = threadIdx.x; k < HID; k += blockDim.x) sh[k] = g_hnew[k];
    __syncthreads();

    int t = (blockIdx.x * blockDim.x + threadIdx.x) >> 5;
    int lane = threadIdx.x & 31;
    if (t >= MAXLEN) return;

    const float4* r = (const float4*)(A + (size_t)t * HID);
    const float4* h4 = (const float4*)sh;
    float a = 0.f;
#pragma unroll
    for (int k = lane; k < HID / 4; k += 32) {
        float4 v = r[k], hv = h4[k];
        a += v.x * hv.x + v.y * hv.y + v.z * hv.z + v.w * hv.w;
    }
    a = warp_sum(a);
    if (lane == 0) g_scores[t] = a;
}

// ---------------- K3: per-block softmax stats (redundant, deterministic) + ctx partials ----------------
// grid 128 = 32 t-chunks (128 t each) x 4 d-chunks (256 d each); 256 threads.
__global__ void k3_ctx_part(const float* __restrict__ A) {
    __shared__ float red[16];
    __shared__ float w_s[128];
    int tid = threadIdx.x;                  // 0..255
    int wid = tid >> 5, lane = tid & 31;
    int bt = blockIdx.x & 31;               // t-chunk
    int bd = blockIdx.x >> 5;               // d-chunk

    // --- stats over all 4096 scores: each thread covers 16 ---
    float m = -INFINITY;
#pragma unroll
    for (int i = 0; i < 16; i++) m = fmaxf(m, g_scores[tid + i * 256]);
    m = warp_max(m);
    if (lane == 0) red[wid] = m;
    __syncthreads();
    if (wid == 0) {
        float v = (lane < 8) ? red[lane] : -INFINITY;
        v = warp_max(v);
        if (lane == 0) red[0] = v;
    }
    __syncthreads();
    m = red[0];
    __syncthreads();

    float l = 0.f;
#pragma unroll
    for (int i = 0; i < 16; i++) l += expf(g_scores[tid + i * 256] - m);
    l = warp_sum(l);
    if (lane == 0) red[wid] = l;
    __syncthreads();
    if (wid == 0) {
        float v = (lane < 8) ? red[lane] : 0.f;
        v = warp_sum(v);
        if (lane == 0) red[1] = 1.f / v;
    }
    __syncthreads();
    float inv_l = red[1];

    // --- weights for this block's 128 timesteps ---
    int t0 = bt * 128;
    if (tid < 128) w_s[tid] = expf(g_scores[t0 + tid] - m) * inv_l;
    __syncthreads();

    // --- weighted accumulation over d-chunk [bd*256, bd*256+256) ---
    int d = bd * 256 + tid;
    float acc = 0.f;
#pragma unroll 4
    for (int t = 0; t < 128; t++)
        acc += A[(size_t)(t0 + t) * HID + d] * w_s[t];
    g_ctx_part[bt * HID + d] = acc;
}

// ---------------- K4: fc1 GEMV with fused ctx reduction ----------------
// 128 blocks x 256 threads; warp per output row.
__global__ void k4_fc1(const float* __restrict__ fc1_w, const float* __restrict__ fc1_b) {
    __shared__ __align__(16) float sc[2 * HID];
    float4* sc4 = (float4*)sc;
    int tid = threadIdx.x;

    // ctx[d] = sum over 32 partials (float4-vectorized, coalesced, MLP=32)
    {
        const float4* part4 = (const float4*)g_ctx_part;
        float4 a = part4[tid];
#pragma unroll
        for (int b = 1; b < NPART; b++) {
            float4 p = part4[b * (HID / 4) + tid];
            a.x += p.x; a.y += p.y; a.z += p.z; a.w += p.w;
        }
        sc4[tid] = a;
        sc4[256 + tid] = ((const float4*)g_hnew)[tid];
    }
    __syncthreads();

    int i = (blockIdx.x * blockDim.x + tid) >> 5;
    int lane = tid & 31;
    if (i >= HID) return;

    const float4* r = (const float4*)(fc1_w + (size_t)i * 2 * HID);
    float a = 0.f;
#pragma unroll
    for (int k = lane; k < (2 * HID) / 4; k += 32) {
        float4 v = r[k], cv = sc4[k];
        a += v.x * cv.x + v.y * cv.y + v.z * cv.z + v.w * cv.w;
    }
    a = warp_sum(a);
    if (lane == 0) g_hid[i] = a + fc1_b[i];
}

// ---------------- K5: fc2 GEMV -> logits, plus per-block lse partials ----------------
__global__ void k5_fc2(const float* __restrict__ fc2_w, const float* __restrict__ fc2_b,
                       float* __restrict__ out) {
    __shared__ __align__(16) float shd[HID];
    __shared__ float s_logit[8];
    for (int k = threadIdx.x; k < HID; k += blockDim.x) shd[k] = g_hid[k];
    __syncthreads();

    int w = threadIdx.x >> 5;
    int lane = threadIdx.x & 31;
    int i = blockIdx.x * 8 + w;

    float logit = -INFINITY;
    if (i < VOCAB) {
        const float4* r = (const float4*)(fc2_w + (size_t)i * HID);
        const float4* h4 = (const float4*)shd;
        float a = 0.f;
#pragma unroll
        for (int k = lane; k < HID / 4; k += 32) {
            float4 v = r[k], hv = h4[k];
            a += v.x * hv.x + v.y * hv.y + v.z * hv.z + v.w * hv.w;
        }
        a = warp_sum(a);
        if (lane == 0) {
            logit = a + fc2_b[i];
            out[i] = logit;
        }
    }
    if (lane == 0) s_logit[w] = logit;
    __syncthreads();

    // warp 0: block-local (m, l) over the 8 logits
    if (threadIdx.x < 32) {
        float v = (lane < 8) ? s_logit[lane] : -INFINITY;
        float m = warp_max(v);
        m = __shfl_sync(0xffffffffu, m, 0);
        float e = (lane < 8 && v > -INFINITY) ? expf(v - m) : 0.f;
        float l = warp_sum(e);
        if (lane == 0) {
            g_lse_m[blockIdx.x] = m;
            g_lse_l[blockIdx.x] = l;
        }
    }
}

// ---------------- K6: single-block reduce of lse partials ----------------
__global__ void k6_lse_reduce() {
    __shared__ float sm[1024];
    __shared__ float sl[1024];
    int tid = threadIdx.x;
    float m = -INFINITY, l = 0.f;
    for (int i = tid; i < K5_BLOCKS; i += 1024) {
        float m2 = g_lse_m[i], l2 = g_lse_l[i];
        float mm = fmaxf(m, m2);
        l = (l > 0.f ? l * expf(m - mm) : 0.f) + (l2 > 0.f ? l2 * expf(m2 - mm) : 0.f);
        m = mm;
    }
    sm[tid] = m;
    sl[tid] = l;
    __syncthreads();
    for (int s = 512; s > 0; s >>= 1) {
        if (tid < s) {
            float m1 = sm[tid], l1 = sl[tid];
            float m2 = sm[tid + s], l2 = sl[tid + s];
            float mm = fmaxf(m1, m2);
            float ll = (l1 > 0.f ? l1 * expf(m1 - mm) : 0.f) +
                       (l2 > 0.f ? l2 * expf(m2 - mm) : 0.f);
            sm[tid] = mm;
            sl[tid] = ll;
        }
        __syncthreads();
    }
    if (tid == 0) g_lse = sm[0] + logf(sl[0]);
}

// ---------------- K7: subtract lse in place ----------------
__global__ void k7_final(float* __restrict__ out) {
    int i = blockIdx.x * blockDim.x + threadIdx.x;
    if (i < VOCAB) out[i] -= g_lse;
}

// ---------------- launch ----------------
extern "C" void kernel_launch(void* const* d_in, const int* in_sizes, int n_in,
                              void* d_out, int out_size) {
    const float* attn  = (const float*)d_in[0];
    const float* x     = (const float*)d_in[1];
    const float* h     = (const float*)d_in[2];
    const float* c     = (const float*)d_in[3];
    const float* W_ih  = (const float*)d_in[4];
    const float* W_hh  = (const float*)d_in[5];
    const float* b_ih  = (const float*)d_in[6];
    const float* b_hh  = (const float*)d_in[7];
    const float* fc1_w = (const float*)d_in[8];
    const float* fc1_b = (const float*)d_in[9];
    const float* fc2_w = (const float*)d_in[10];
    const float* fc2_b = (const float*)d_in[11];
    float* out = (float*)d_out;

    k1_lstm<<<256, 128>>>(W_ih, W_hh, b_ih, b_hh, x, h, c, out + VOCAB);
    k2_scores<<<512, 256>>>(attn);
    k3_ctx_part<<<128, 256>>>(attn);
    k4_fc1<<<128, 256>>>(fc1_w, fc1_b);
    k5_fc2<<<K5_BLOCKS, 256>>>(fc2_w, fc2_b, out);
    k6_lse_reduce<<<1, 1024>>>();
    k7_final<<<(VOCAB + 255) / 256, 256>>>(out);
}

// round 6
// speedup vs baseline: 1.0178x; 1.0178x over previous
#include <cuda_runtime.h>
#include <math.h>

#define HID 1024
#define EMB 1024
#define MAXLEN 4096
#define VOCAB 50257
#define NPART 8                       // ctx partial slices (t-chunks)
#define K5_ROWS 16
#define K5_BLOCKS ((VOCAB + K5_ROWS - 1) / K5_ROWS)   // 3142

// ---------------- device scratch ----------------
__device__ float g_hnew[HID];
__device__ float g_scores[MAXLEN];
__device__ float g_ctx_part[NPART * HID];
__device__ float g_hid[HID];
__device__ float g_lse_m[K5_BLOCKS];
__device__ float g_lse_l[K5_BLOCKS];

__device__ __forceinline__ float warp_sum(float v) {
#pragma unroll
    for (int o = 16; o; o >>= 1) v += __shfl_down_sync(0xffffffffu, v, o);
    return v;
}
__device__ __forceinline__ float warp_max(float v) {
#pragma unroll
    for (int o = 16; o; o >>= 1) v = fmaxf(v, __shfl_down_sync(0xffffffffu, v, o));
    return v;
}

__device__ __forceinline__ float sigmoidf(float x) { return 1.f / (1.f + expf(-x)); }

// ---------------- K1: gates GEMV + LSTM pointwise ----------------
__global__ void k1_lstm(const float* __restrict__ W_ih, const float* __restrict__ W_hh,
                        const float* __restrict__ b_ih, const float* __restrict__ b_hh,
                        const float* __restrict__ x, const float* __restrict__ h,
                        const float* __restrict__ c, float* __restrict__ out_tail) {
    __shared__ __align__(16) float sx[EMB];
    __shared__ __align__(16) float sh[HID];
    for (int k = threadIdx.x; k < EMB; k += blockDim.x) sx[k] = x[k];
    for (int k = threadIdx.x; k < HID; k += blockDim.x) sh[k] = h[k];
    __syncthreads();

    int j = (blockIdx.x * blockDim.x + threadIdx.x) >> 5;
    int lane = threadIdx.x & 31;
    if (j >= HID) return;

    const float4* x4 = (const float4*)sx;
    const float4* h4 = (const float4*)sh;
    float acc[4];
#pragma unroll
    for (int g = 0; g < 4; g++) {
        const float4* rW = (const float4*)(W_ih + (size_t)(g * HID + j) * EMB);
        const float4* rU = (const float4*)(W_hh + (size_t)(g * HID + j) * HID);
        float a = 0.f;
#pragma unroll
        for (int k = lane; k < EMB / 4; k += 32) {
            float4 w = rW[k], xv = x4[k];
            a += w.x * xv.x + w.y * xv.y + w.z * xv.z + w.w * xv.w;
            float4 u = rU[k], hv = h4[k];
            a += u.x * hv.x + u.y * hv.y + u.z * hv.z + u.w * hv.w;
        }
        acc[g] = warp_sum(a);
    }
    if (lane == 0) {
        float gi = acc[0] + b_ih[j]           + b_hh[j];
        float gf = acc[1] + b_ih[HID + j]     + b_hh[HID + j];
        float gg = acc[2] + b_ih[2 * HID + j] + b_hh[2 * HID + j];
        float go = acc[3] + b_ih[3 * HID + j] + b_hh[3 * HID + j];
        float ig = sigmoidf(gi);
        float fg = sigmoidf(gf);
        float gt = tanhf(gg);
        float og = sigmoidf(go);
        float cn = fg * c[j] + ig * gt;
        float hn = og * tanhf(cn);
        g_hnew[j] = hn;
        out_tail[j] = hn;          // h_new
        out_tail[HID + j] = cn;    // c_new
    }
}

// ---------------- K2: scores[t] = dot(A[t,:], h_new) ----------------
__global__ void k2_scores(const float* __restrict__ A) {
    __shared__ __align__(16) float sh[HID];
    for (int k = threadIdx.x; k < HID; k += blockDim.x) sh[k] = g_hnew[k];
    __syncthreads();

    int t = (blockIdx.x * blockDim.x + threadIdx.x) >> 5;
    int lane = threadIdx.x & 31;
    if (t >= MAXLEN) return;

    const float4* r = (const float4*)(A + (size_t)t * HID);
    const float4* h4 = (const float4*)sh;
    float a = 0.f;
#pragma unroll
    for (int k = lane; k < HID / 4; k += 32) {
        float4 v = r[k], hv = h4[k];
        a += v.x * hv.x + v.y * hv.y + v.z * hv.z + v.w * hv.w;
    }
    a = warp_sum(a);
    if (lane == 0) g_scores[t] = a;
}

// ---------------- K3: per-block softmax stats (redundant, deterministic) + ctx partials ----------------
// grid 128 = 8 t-chunks (512 t each) x 16 d-chunks (64 d each); 256 threads = 4 t-sub x 64 d.
// Writes only NPART=8 partials per d.
__global__ void k3_ctx_part(const float* __restrict__ A) {
    __shared__ float red[8];
    __shared__ float w_s[512];
    __shared__ float sred[4][64];
    int tid = threadIdx.x;                  // 0..255
    int wid = tid >> 5, lane = tid & 31;
    int bt = blockIdx.x >> 4;               // t-chunk 0..7
    int bd = blockIdx.x & 15;               // d-chunk 0..15

    // --- stats over all 4096 scores: each thread covers 16 ---
    float m = -INFINITY;
#pragma unroll
    for (int i = 0; i < 16; i++) m = fmaxf(m, g_scores[tid + i * 256]);
    m = warp_max(m);
    if (lane == 0) red[wid] = m;
    __syncthreads();
    if (wid == 0) {
        float v = (lane < 8) ? red[lane] : -INFINITY;
        v = warp_max(v);
        if (lane == 0) red[0] = v;
    }
    __syncthreads();
    m = red[0];
    __syncthreads();

    float l = 0.f;
#pragma unroll
    for (int i = 0; i < 16; i++) l += expf(g_scores[tid + i * 256] - m);
    l = warp_sum(l);
    if (lane == 0) red[wid] = l;
    __syncthreads();
    if (wid == 0) {
        float v = (lane < 8) ? red[lane] : 0.f;
        v = warp_sum(v);
        if (lane == 0) red[1] = 1.f / v;
    }
    __syncthreads();
    float inv_l = red[1];

    // --- weights for this t-chunk's 512 timesteps ---
    int t0 = bt * 512;
#pragma unroll
    for (int i = tid; i < 512; i += 256) w_s[i] = expf(g_scores[t0 + i] - m) * inv_l;
    __syncthreads();

    // --- weighted accumulation: t-sub covers 128 timesteps, 64 d values ---
    int tsub = tid >> 6;        // 0..3
    int dl = tid & 63;          // 0..63
    int d = bd * 64 + dl;
    float acc = 0.f;
    int tb = tsub * 128;
#pragma unroll 4
    for (int t = 0; t < 128; t++)
        acc += A[(size_t)(t0 + tb + t) * HID + d] * w_s[tb + t];
    sred[tsub][dl] = acc;
    __syncthreads();

    if (tsub == 0)
        g_ctx_part[bt * HID + d] = sred[0][dl] + sred[1][dl] + sred[2][dl] + sred[3][dl];
}

// ---------------- K4: fc1 GEMV with cheap fused ctx reduction (8 partials) ----------------
// 256 blocks x 128 threads; warp per output row (4 rows/block).
__global__ void k4_fc1(const float* __restrict__ fc1_w, const float* __restrict__ fc1_b) {
    __shared__ __align__(16) float sc[2 * HID];
    float4* sc4 = (float4*)sc;
    int tid = threadIdx.x;

    // ctx: 256 float4 entries, 128 threads -> 2 each, sum of 8 partials (MLP=8+)
    const float4* part4 = (const float4*)g_ctx_part;
#pragma unroll
    for (int j = tid; j < 256; j += 128) {
        float4 a = part4[j];
#pragma unroll
        for (int b = 1; b < NPART; b++) {
            float4 p = part4[b * 256 + j];
            a.x += p.x; a.y += p.y; a.z += p.z; a.w += p.w;
        }
        sc4[j] = a;
    }
    const float4* hn4 = (const float4*)g_hnew;
#pragma unroll
    for (int j = tid; j < 256; j += 128) sc4[256 + j] = hn4[j];
    __syncthreads();

    int i = blockIdx.x * 4 + (tid >> 5);
    int lane = tid & 31;
    if (i >= HID) return;

    const float4* r = (const float4*)(fc1_w + (size_t)i * 2 * HID);
    float a = 0.f;
#pragma unroll
    for (int k = lane; k < (2 * HID) / 4; k += 32) {
        float4 v = r[k], cv = sc4[k];
        a += v.x * cv.x + v.y * cv.y + v.z * cv.z + v.w * cv.w;
    }
    a = warp_sum(a);
    if (lane == 0) g_hid[i] = a + fc1_b[i];
}

// ---------------- K5: fc2 GEMV -> logits, plus per-block lse partials ----------------
// 512 threads, 16 rows per block.
__global__ void k5_fc2(const float* __restrict__ fc2_w, const float* __restrict__ fc2_b,
                       float* __restrict__ out) {
    __shared__ __align__(16) float shd[HID];
    __shared__ float s_logit[K5_ROWS];
    for (int k = threadIdx.x; k < HID; k += blockDim.x) shd[k] = g_hid[k];
    __syncthreads();

    int w = threadIdx.x >> 5;
    int lane = threadIdx.x & 31;
    int i = blockIdx.x * K5_ROWS + w;

    float logit = -INFINITY;
    if (i < VOCAB) {
        const float4* r = (const float4*)(fc2_w + (size_t)i * HID);
        const float4* h4 = (const float4*)shd;
        float a = 0.f;
#pragma unroll
        for (int k = lane; k < HID / 4; k += 32) {
            float4 v = r[k], hv = h4[k];
            a += v.x * hv.x + v.y * hv.y + v.z * hv.z + v.w * hv.w;
        }
        a = warp_sum(a);
        if (lane == 0) {
            logit = a + fc2_b[i];
            out[i] = logit;
        }
    }
    if (lane == 0) s_logit[w] = logit;
    __syncthreads();

    // warp 0: block-local (m, l) over the 16 logits
    if (threadIdx.x < 32) {
        float v = (lane < K5_ROWS) ? s_logit[lane] : -INFINITY;
        float m = warp_max(v);
        m = __shfl_sync(0xffffffffu, m, 0);
        float e = (lane < K5_ROWS && v > -INFINITY) ? expf(v - m) : 0.f;
        float l = warp_sum(e);
        if (lane == 0) {
            g_lse_m[blockIdx.x] = m;
            g_lse_l[blockIdx.x] = l;
        }
    }
}

// ---------------- K7: redundant lse reduce per block + subtract in place ----------------
// 99 blocks x 512 threads; each block reduces all 3142 (m,l) pairs (L2-resident), deterministic.
__global__ void k7_final(float* __restrict__ out) {
    __shared__ float sm[512];
    __shared__ float sl[512];
    int tid = threadIdx.x;
    float m = -INFINITY, l = 0.f;
    for (int i = tid; i < K5_BLOCKS; i += 512) {
        float m2 = g_lse_m[i], l2 = g_lse_l[i];
        float mm = fmaxf(m, m2);
        l = (l > 0.f ? l * expf(m - mm) : 0.f) + (l2 > 0.f ? l2 * expf(m2 - mm) : 0.f);
        m = mm;
    }
    sm[tid] = m;
    sl[tid] = l;
    __syncthreads();
    for (int s = 256; s > 0; s >>= 1) {
        if (tid < s) {
            float m1 = sm[tid], l1 = sl[tid];
            float m2 = sm[tid + s], l2 = sl[tid + s];
            float mm = fmaxf(m1, m2);
            float ll = (l1 > 0.f ? l1 * expf(m1 - mm) : 0.f) +
                       (l2 > 0.f ? l2 * expf(m2 - mm) : 0.f);
            sm[tid] = mm;
            sl[tid] = ll;
        }
        __syncthreads();
    }
    float lse = sm[0] + logf(sl[0]);
    int i = blockIdx.x * 512 + tid;
    if (i < VOCAB) out[i] -= lse;
}

// ---------------- launch ----------------
extern "C" void kernel_launch(void* const* d_in, const int* in_sizes, int n_in,
                              void* d_out, int out_size) {
    const float* attn  = (const float*)d_in[0];
    const float* x     = (const float*)d_in[1];
    const float* h     = (const float*)d_in[2];
    const float* c     = (const float*)d_in[3];
    const float* W_ih  = (const float*)d_in[4];
    const float* W_hh  = (const float*)d_in[5];
    const float* b_ih  = (const float*)d_in[6];
    const float* b_hh  = (const float*)d_in[7];
    const float* fc1_w = (const float*)d_in[8];
    const float* fc1_b = (const float*)d_in[9];
    const float* fc2_w = (const float*)d_in[10];
    const float* fc2_b = (const float*)d_in[11];
    float* out = (float*)d_out;

    k1_lstm<<<256, 128>>>(W_ih, W_hh, b_ih, b_hh, x, h, c, out + VOCAB);
    k2_scores<<<512, 256>>>(attn);
    k3_ctx_part<<<128, 256>>>(attn);
    k4_fc1<<<256, 128>>>(fc1_w, fc1_b);
    k5_fc2<<<K5_BLOCKS, 512>>>(fc2_w, fc2_b, out);
    k7_final<<<(VOCAB + 511) / 512, 512>>>(out);
}

// round 7
// speedup vs baseline: 1.3910x; 1.3666x over previous
#include <cuda_runtime.h>
#include <math.h>

#define HID 1024
#define EMB 1024
#define MAXLEN 4096
#define VOCAB 50257
#define NBLK 128
#define NTHR 1024
#define NPART 8

// ---------------- device scratch ----------------
__device__ float g_hnew[HID];
__device__ float g_scores[MAXLEN];
__device__ float g_ctx_part[NPART * HID];
__device__ float g_hid[HID];
__device__ float g_lse_m[NBLK];
__device__ float g_lse_l[NBLK];
__device__ unsigned long long g_bar = 0ULL;   // monotonic ticket counter (never reset)

__device__ __forceinline__ float warp_sum(float v) {
#pragma unroll
    for (int o = 16; o; o >>= 1) v += __shfl_down_sync(0xffffffffu, v, o);
    return v;
}
__device__ __forceinline__ float warp_max(float v) {
#pragma unroll
    for (int o = 16; o; o >>= 1) v = fmaxf(v, __shfl_down_sync(0xffffffffu, v, o));
    return v;
}

// deterministic, reset-free grid barrier (all NBLK blocks co-resident by construction)
__device__ __forceinline__ void grid_barrier() {
    __syncthreads();
    if (threadIdx.x == 0) {
        __threadfence();
        unsigned long long ticket = atomicAdd(&g_bar, 1ULL);
        unsigned long long target = (ticket / NBLK + 1ULL) * (unsigned long long)NBLK;
        while (*(volatile unsigned long long*)&g_bar < target) { }
    }
    __syncthreads();
}

__global__ __launch_bounds__(NTHR, 1)
void fused_all(const float* __restrict__ A, const float* __restrict__ x,
               const float* __restrict__ h, const float* __restrict__ c,
               const float* __restrict__ W_ih, const float* __restrict__ W_hh,
               const float* __restrict__ b_ih, const float* __restrict__ b_hh,
               const float* __restrict__ fc1_w, const float* __restrict__ fc1_b,
               const float* __restrict__ fc2_w, const float* __restrict__ fc2_b,
               float* __restrict__ out)
{
    __shared__ __align__(16) float svec[2 * HID];  // 8 KB staging
    __shared__ __align__(16) float sws[512];       // softmax weights
    __shared__ float sred[16][64];                 // ctx / fc1 partial reduce
    __shared__ float sgate[4][8];
    __shared__ float sredw[32];
    __shared__ float sredw2[32];

    const int tid = threadIdx.x;
    const int b = blockIdx.x;
    const int w = tid >> 5, lane = tid & 31;

    // ================= Phase 1: LSTM (gates + pointwise, intra-block) =================
    svec[tid] = x[tid];
    svec[HID + tid] = h[tid];
    __syncthreads();
    {
        int jl = w & 7, g = w >> 3;              // 8 hidden units, 4 gates per block
        int j = b * 8 + jl;
        int row = g * HID + j;
        const float4* rW = (const float4*)(W_ih + (size_t)row * EMB);
        const float4* rU = (const float4*)(W_hh + (size_t)row * HID);
        const float4* x4 = (const float4*)svec;
        const float4* h4 = (const float4*)(svec + HID);
        float a = 0.f;
#pragma unroll 4
        for (int k = lane; k < 256; k += 32) {
            float4 wv = rW[k], xv = x4[k];
            a += wv.x * xv.x + wv.y * xv.y + wv.z * xv.z + wv.w * xv.w;
            float4 uv = rU[k], hv = h4[k];
            a += uv.x * hv.x + uv.y * hv.y + uv.z * hv.z + uv.w * hv.w;
        }
        a = warp_sum(a);
        if (lane == 0) sgate[g][jl] = a;
    }
    __syncthreads();
    if (tid < 8) {
        int j = b * 8 + tid;
        float gi = sgate[0][tid] + b_ih[j]           + b_hh[j];
        float gf = sgate[1][tid] + b_ih[HID + j]     + b_hh[HID + j];
        float gg = sgate[2][tid] + b_ih[2 * HID + j] + b_hh[2 * HID + j];
        float go = sgate[3][tid] + b_ih[3 * HID + j] + b_hh[3 * HID + j];
        float ig = 1.f / (1.f + expf(-gi));
        float fg = 1.f / (1.f + expf(-gf));
        float gt = tanhf(gg);
        float og = 1.f / (1.f + expf(-go));
        float cn = fg * c[j] + ig * gt;
        float hn = og * tanhf(cn);
        g_hnew[j] = hn;
        out[VOCAB + j] = hn;
        out[VOCAB + HID + j] = cn;
    }
    grid_barrier();

    // ================= Phase 2: scores[t] = A[t,:] . h_new =================
    svec[tid] = g_hnew[tid];
    __syncthreads();
    {
        int t = b * 32 + w;                      // 128*32 = 4096
        const float4* r = (const float4*)(A + (size_t)t * HID);
        const float4* h4 = (const float4*)svec;
        float a = 0.f;
#pragma unroll
        for (int k = lane; k < 256; k += 32) {
            float4 v = r[k], hv = h4[k];
            a += v.x * hv.x + v.y * hv.y + v.z * hv.z + v.w * hv.w;
        }
        a = warp_sum(a);
        if (lane == 0) g_scores[t] = a;
    }
    grid_barrier();

    // ================= Phase 3: softmax stats (redundant per block) + ctx partials =================
    float m, inv_l;
    {
        float mm = -INFINITY;
#pragma unroll
        for (int i = 0; i < 4; i++) mm = fmaxf(mm, g_scores[tid + i * 1024]);
        mm = warp_max(mm);
        if (lane == 0) sredw[w] = mm;
        __syncthreads();
        if (w == 0) {
            float v = sredw[lane];
            v = warp_max(v);
            if (lane == 0) sredw[0] = v;
        }
        __syncthreads();
        m = sredw[0];
        __syncthreads();

        float l = 0.f;
#pragma unroll
        for (int i = 0; i < 4; i++) l += expf(g_scores[tid + i * 1024] - m);
        l = warp_sum(l);
        if (lane == 0) sredw2[w] = l;
        __syncthreads();
        if (w == 0) {
            float v = sredw2[lane];
            v = warp_sum(v);
            if (lane == 0) sredw2[0] = 1.f / v;
        }
        __syncthreads();
        inv_l = sredw2[0];
    }
    {
        int bt = b >> 4;                         // t-chunk 0..7 (512 t each)
        int bd = b & 15;                         // d-chunk 0..15 (64 d each)
        int t0 = bt * 512;
        if (tid < 512) sws[tid] = expf(g_scores[t0 + tid] - m) * inv_l;
        __syncthreads();

        int tsub = tid >> 6;                     // 0..15, 32 t each
        int dl = tid & 63;
        int d = bd * 64 + dl;
        float acc = 0.f;
        int tb = tsub * 32;
#pragma unroll 4
        for (int t = 0; t < 32; t++)
            acc += A[(size_t)(t0 + tb + t) * HID + d] * sws[tb + t];
        sred[tsub][dl] = acc;
        __syncthreads();
        if (tid < 64) {
            float v = 0.f;
#pragma unroll
            for (int k2 = 0; k2 < 16; k2++) v += sred[k2][tid];
            g_ctx_part[bt * HID + bd * 64 + tid] = v;
        }
    }
    grid_barrier();

    // ================= Phase 4: fc1 (fused ctx reduce; 8 rows/block, 4 warps/row) =================
    {
        float4* sc4 = (float4*)svec;
        if (tid < 256) {
            const float4* part4 = (const float4*)g_ctx_part;
            float4 a = part4[tid];
#pragma unroll
            for (int s = 1; s < NPART; s++) {
                float4 p = part4[s * 256 + tid];
                a.x += p.x; a.y += p.y; a.z += p.z; a.w += p.w;
            }
            sc4[tid] = a;
        } else if (tid < 512) {
            sc4[tid] = ((const float4*)g_hnew)[tid - 256];
        }
        __syncthreads();

        int jl = w >> 2;                         // row within block 0..7
        int q = w & 3;                           // quarter of K
        int j = b * 8 + jl;
        const float4* r = (const float4*)(fc1_w + (size_t)j * 2 * HID);
        float a = 0.f;
#pragma unroll
        for (int k = q * 128 + lane; k < (q + 1) * 128; k += 32) {
            float4 v = r[k], cv = sc4[k];
            a += v.x * cv.x + v.y * cv.y + v.z * cv.z + v.w * cv.w;
        }
        a = warp_sum(a);
        if (lane == 0) sred[0][w] = a;
        __syncthreads();
        if (tid < 8) {
            float v = sred[0][tid * 4] + sred[0][tid * 4 + 1] +
                      sred[0][tid * 4 + 2] + sred[0][tid * 4 + 3];
            g_hid[b * 8 + tid] = v + fc1_b[b * 8 + tid];
        }
    }
    grid_barrier();

    // ================= Phase 5: fc2 + per-block LSE partials =================
    {
        svec[tid] = g_hid[tid];
        __syncthreads();
        const float4* h4 = (const float4*)svec;
        int gw = b * 32 + w;                     // global warp 0..4095
        float lm = -INFINITY, ll = 0.f;
        for (int r0 = gw; r0 < VOCAB; r0 += 4096) {
            const float4* r = (const float4*)(fc2_w + (size_t)r0 * HID);
            float a = 0.f;
#pragma unroll
            for (int k = lane; k < 256; k += 32) {
                float4 v = r[k], hv = h4[k];
                a += v.x * hv.x + v.y * hv.y + v.z * hv.z + v.w * hv.w;
            }
            a = warp_sum(a);
            if (lane == 0) {
                float logit = a + fc2_b[r0];
                out[r0] = logit;
                float mm = fmaxf(lm, logit);
                ll = ll * expf(lm - mm) + expf(logit - mm);
                lm = mm;
            }
        }
        if (lane == 0) { sredw[w] = lm; sredw2[w] = ll; }
        __syncthreads();
        if (w == 0) {
            float mm = sredw[lane], lll = sredw2[lane];
#pragma unroll
            for (int o = 16; o; o >>= 1) {
                float m2 = __shfl_down_sync(0xffffffffu, mm, o);
                float l2 = __shfl_down_sync(0xffffffffu, lll, o);
                float M = fmaxf(mm, m2);
                lll = lll * expf(mm - M) + l2 * expf(m2 - M);
                mm = M;
            }
            if (lane == 0) { g_lse_m[b] = mm; g_lse_l[b] = lll; }
        }
    }
    grid_barrier();

    // ================= Phase 6: LSE combine (redundant per block) + subtract =================
    {
        if (w == 0) {
            float mm = -INFINITY, lll = 0.f;
#pragma unroll
            for (int i = 0; i < 4; i++) {
                float m2 = g_lse_m[lane + i * 32], l2 = g_lse_l[lane + i * 32];
                float M = fmaxf(mm, m2);
                lll = lll * expf(mm - M) + l2 * expf(m2 - M);
                mm = M;
            }
#pragma unroll
            for (int o = 16; o; o >>= 1) {
                float m2 = __shfl_down_sync(0xffffffffu, mm, o);
                float l2 = __shfl_down_sync(0xffffffffu, lll, o);
                float M = fmaxf(mm, m2);
                lll = lll * expf(mm - M) + l2 * expf(m2 - M);
                mm = M;
            }
            if (lane == 0) sredw[0] = mm + logf(lll);
        }
        __syncthreads();
        float lse = sredw[0];
        int i = b * NTHR + tid;
        if (i < VOCAB) out[i] -= lse;
    }
}

// ---------------- launch ----------------
extern "C" void kernel_launch(void* const* d_in, const int* in_sizes, int n_in,
                              void* d_out, int out_size) {
    const float* attn  = (const float*)d_in[0];
    const float* x     = (const float*)d_in[1];
    const float* h     = (const float*)d_in[2];
    const float* c     = (const float*)d_in[3];
    const float* W_ih  = (const float*)d_in[4];
    const float* W_hh  = (const float*)d_in[5];
    const float* b_ih  = (const float*)d_in[6];
    const float* b_hh  = (const float*)d_in[7];
    const float* fc1_w = (const float*)d_in[8];
    const float* fc1_b = (const float*)d_in[9];
    const float* fc2_w = (const float*)d_in[10];
    const float* fc2_b = (const float*)d_in[11];
    float* out = (float*)d_out;

    fused_all<<<NBLK, NTHR>>>(attn, x, h, c, W_ih, W_hh, b_ih, b_hh,
                              fc1_w, fc1_b, fc2_w, fc2_b, out);
}

// round 8
// speedup vs baseline: 1.4799x; 1.0639x over previous
#include <cuda_runtime.h>
#include <math.h>

#define HID 1024
#define EMB 1024
#define MAXLEN 4096
#define VOCAB 50257
#define NBLK 148
#define NTHR 1024
#define NPART 8
#define NWARPS (NBLK * 32)    // 4736 warps

// ---------------- device scratch ----------------
__device__ float g_hnew[HID];
__device__ float g_scores[MAXLEN];
__device__ float g_ctx_part[NPART * HID];
__device__ float g_hid[HID];
__device__ float g_lse_m[NBLK];
__device__ float g_lse_l[NBLK];
__device__ unsigned long long g_bar = 0ULL;   // monotonic ticket counter (never reset)

__device__ __forceinline__ float warp_sum(float v) {
#pragma unroll
    for (int o = 16; o; o >>= 1) v += __shfl_down_sync(0xffffffffu, v, o);
    return v;
}
__device__ __forceinline__ float warp_max(float v) {
#pragma unroll
    for (int o = 16; o; o >>= 1) v = fmaxf(v, __shfl_down_sync(0xffffffffu, v, o));
    return v;
}

// deterministic, reset-free grid barrier (all NBLK blocks co-resident: 148 blocks, 1/SM)
__device__ __forceinline__ void grid_barrier() {
    __syncthreads();
    if (threadIdx.x == 0) {
        __threadfence();
        unsigned long long ticket = atomicAdd(&g_bar, 1ULL);
        unsigned long long target = (ticket / NBLK + 1ULL) * (unsigned long long)NBLK;
        while (*(volatile unsigned long long*)&g_bar < target) { }
    }
    __syncthreads();
}

__global__ __launch_bounds__(NTHR, 1)
void fused_all(const float* __restrict__ A, const float* __restrict__ x,
               const float* __restrict__ h, const float* __restrict__ c,
               const float* __restrict__ W_ih, const float* __restrict__ W_hh,
               const float* __restrict__ b_ih, const float* __restrict__ b_hh,
               const float* __restrict__ fc1_w, const float* __restrict__ fc1_b,
               const float* __restrict__ fc2_w, const float* __restrict__ fc2_b,
               float* __restrict__ out)
{
    __shared__ __align__(16) float svec[2 * HID];  // 8 KB staging
    __shared__ __align__(16) float sws[512];       // softmax weights
    __shared__ float sred[16][64];                 // ctx / fc1 partial reduce
    __shared__ float sgate[4][8];
    __shared__ float sredw[32];
    __shared__ float sredw2[32];

    const int tid = threadIdx.x;
    const int b = blockIdx.x;
    const int w = tid >> 5, lane = tid & 31;

    // ================= Phase 1: LSTM (gates + pointwise, intra-block; blocks 0..127) =================
    if (b < 128) {
        svec[tid] = x[tid];
        svec[HID + tid] = h[tid];
        __syncthreads();
        {
            int jl = w & 7, g = w >> 3;              // 8 hidden units, 4 gates per block
            int j = b * 8 + jl;
            int row = g * HID + j;
            const float4* rW = (const float4*)(W_ih + (size_t)row * EMB);
            const float4* rU = (const float4*)(W_hh + (size_t)row * HID);
            const float4* x4 = (const float4*)svec;
            const float4* h4 = (const float4*)(svec + HID);
            float a = 0.f;
#pragma unroll
            for (int k = lane; k < 256; k += 32) {
                float4 wv = __ldcs(rW + k), xv = x4[k];
                a += wv.x * xv.x + wv.y * xv.y + wv.z * xv.z + wv.w * xv.w;
                float4 uv = __ldcs(rU + k), hv = h4[k];
                a += uv.x * hv.x + uv.y * hv.y + uv.z * hv.z + uv.w * hv.w;
            }
            a = warp_sum(a);
            if (lane == 0) sgate[g][jl] = a;
        }
        __syncthreads();
        if (tid < 8) {
            int j = b * 8 + tid;
            float gi = sgate[0][tid] + b_ih[j]           + b_hh[j];
            float gf = sgate[1][tid] + b_ih[HID + j]     + b_hh[HID + j];
            float gg = sgate[2][tid] + b_ih[2 * HID + j] + b_hh[2 * HID + j];
            float go = sgate[3][tid] + b_ih[3 * HID + j] + b_hh[3 * HID + j];
            float ig = 1.f / (1.f + expf(-gi));
            float fg = 1.f / (1.f + expf(-gf));
            float gt = tanhf(gg);
            float og = 1.f / (1.f + expf(-go));
            float cn = fg * c[j] + ig * gt;
            float hn = og * tanhf(cn);
            g_hnew[j] = hn;
            out[VOCAB + j] = hn;
            out[VOCAB + HID + j] = cn;
        }
    }
    grid_barrier();

    // ================= Phase 2: scores[t] = A[t,:] . h_new (all 148 blocks) =================
    svec[tid] = g_hnew[tid];
    __syncthreads();
    {
        int t = b * 32 + w;                      // 0..4735
        if (t < MAXLEN) {
            const float4* r = (const float4*)(A + (size_t)t * HID);
            const float4* h4 = (const float4*)svec;
            float a = 0.f;
#pragma unroll
            for (int k = lane; k < 256; k += 32) {
                float4 v = r[k], hv = h4[k];
                a += v.x * hv.x + v.y * hv.y + v.z * hv.z + v.w * hv.w;
            }
            a = warp_sum(a);
            if (lane == 0) g_scores[t] = a;
        }
    }
    grid_barrier();

    // ================= Phase 3: softmax stats (redundant per block) + ctx partials (blocks 0..127) =================
    if (b < 128) {
        float m, inv_l;
        {
            float mm = -INFINITY;
#pragma unroll
            for (int i = 0; i < 4; i++) mm = fmaxf(mm, g_scores[tid + i * 1024]);
            mm = warp_max(mm);
            if (lane == 0) sredw[w] = mm;
            __syncthreads();
            if (w == 0) {
                float v = sredw[lane];
                v = warp_max(v);
                if (lane == 0) sredw[0] = v;
            }
            __syncthreads();
            m = sredw[0];
            __syncthreads();

            float l = 0.f;
#pragma unroll
            for (int i = 0; i < 4; i++) l += expf(g_scores[tid + i * 1024] - m);
            l = warp_sum(l);
            if (lane == 0) sredw2[w] = l;
            __syncthreads();
            if (w == 0) {
                float v = sredw2[lane];
                v = warp_sum(v);
                if (lane == 0) sredw2[0] = 1.f / v;
            }
            __syncthreads();
            inv_l = sredw2[0];
        }
        {
            int bt = b >> 4;                         // t-chunk 0..7 (512 t each)
            int bd = b & 15;                         // d-chunk 0..15 (64 d each)
            int t0 = bt * 512;
            if (tid < 512) sws[tid] = expf(g_scores[t0 + tid] - m) * inv_l;
            __syncthreads();

            int tsub = tid >> 6;                     // 0..15, 32 t each
            int dl = tid & 63;
            int d = bd * 64 + dl;
            float acc = 0.f;
            int tb = tsub * 32;
#pragma unroll 4
            for (int t = 0; t < 32; t++)
                acc += A[(size_t)(t0 + tb + t) * HID + d] * sws[tb + t];
            sred[tsub][dl] = acc;
            __syncthreads();
            if (tid < 64) {
                float v = 0.f;
#pragma unroll
                for (int k2 = 0; k2 < 16; k2++) v += sred[k2][tid];
                g_ctx_part[bt * HID + bd * 64 + tid] = v;
            }
        }
    }
    grid_barrier();

    // ================= Phase 4: fc1 (fused ctx reduce; blocks 0..127, 8 rows each) =================
    if (b < 128) {
        float4* sc4 = (float4*)svec;
        if (tid < 256) {
            const float4* part4 = (const float4*)g_ctx_part;
            float4 a = part4[tid];
#pragma unroll
            for (int s = 1; s < NPART; s++) {
                float4 p = part4[s * 256 + tid];
                a.x += p.x; a.y += p.y; a.z += p.z; a.w += p.w;
            }
            sc4[tid] = a;
        } else if (tid < 512) {
            sc4[tid] = ((const float4*)g_hnew)[tid - 256];
        }
        __syncthreads();

        int jl = w >> 2;                         // row within block 0..7
        int q = w & 3;                           // quarter of K
        int j = b * 8 + jl;
        const float4* r = (const float4*)(fc1_w + (size_t)j * 2 * HID);
        float a = 0.f;
#pragma unroll
        for (int k = q * 128 + lane; k < (q + 1) * 128; k += 32) {
            float4 v = __ldcs(r + k), cv = sc4[k];
            a += v.x * cv.x + v.y * cv.y + v.z * cv.z + v.w * cv.w;
        }
        a = warp_sum(a);
        if (lane == 0) sred[0][w] = a;
        __syncthreads();
        if (tid < 8) {
            float v = sred[0][tid * 4] + sred[0][tid * 4 + 1] +
                      sred[0][tid * 4 + 2] + sred[0][tid * 4 + 3];
            g_hid[b * 8 + tid] = v + fc1_b[b * 8 + tid];
        }
    }
    grid_barrier();

    // ================= Phase 5: fc2 (2 rows/warp, streaming loads) + per-block LSE =================
    {
        svec[tid] = g_hid[tid];
        __syncthreads();
        const float4* h4 = (const float4*)svec;
        int gw = b * 32 + w;                     // global warp 0..4735
        float lm = -INFINITY, ll = 0.f;
        for (int r0 = gw; r0 < VOCAB; r0 += 2 * NWARPS) {
            int r1 = r0 + NWARPS;
            bool has1 = (r1 < VOCAB);
            const float4* p0 = (const float4*)(fc2_w + (size_t)r0 * HID);
            const float4* p1 = (const float4*)(fc2_w + (size_t)(has1 ? r1 : r0) * HID);
            float a0 = 0.f, a1 = 0.f;
#pragma unroll
            for (int k = lane; k < 256; k += 32) {
                float4 v0 = __ldcs(p0 + k);
                float4 v1 = __ldcs(p1 + k);
                float4 hv = h4[k];
                a0 += v0.x * hv.x + v0.y * hv.y + v0.z * hv.z + v0.w * hv.w;
                a1 += v1.x * hv.x + v1.y * hv.y + v1.z * hv.z + v1.w * hv.w;
            }
            a0 = warp_sum(a0);
            a1 = warp_sum(a1);
            if (lane == 0) {
                float logit0 = a0 + fc2_b[r0];
                out[r0] = logit0;
                float mm = fmaxf(lm, logit0);
                ll = ll * expf(lm - mm) + expf(logit0 - mm);
                lm = mm;
                if (has1) {
                    float logit1 = a1 + fc2_b[r1];
                    out[r1] = logit1;
                    mm = fmaxf(lm, logit1);
                    ll = ll * expf(lm - mm) + expf(logit1 - mm);
                    lm = mm;
                }
            }
        }
        if (lane == 0) { sredw[w] = lm; sredw2[w] = ll; }
        __syncthreads();
        if (w == 0) {
            float mm = sredw[lane], lll = sredw2[lane];
#pragma unroll
            for (int o = 16; o; o >>= 1) {
                float m2 = __shfl_down_sync(0xffffffffu, mm, o);
                float l2 = __shfl_down_sync(0xffffffffu, lll, o);
                float M = fmaxf(mm, m2);
                lll = lll * expf(mm - M) + l2 * expf(m2 - M);
                mm = M;
            }
            if (lane == 0) { g_lse_m[b] = mm; g_lse_l[b] = lll; }
        }
    }
    grid_barrier();

    // ================= Phase 6: LSE combine (redundant per block) + subtract =================
    {
        if (w == 0) {
            float mm = -INFINITY, lll = 0.f;
            for (int i = lane; i < NBLK; i += 32) {
                float m2 = g_lse_m[i], l2 = g_lse_l[i];
                float M = fmaxf(mm, m2);
                lll = lll * expf(mm - M) + l2 * expf(m2 - M);
                mm = M;
            }
#pragma unroll
            for (int o = 16; o; o >>= 1) {
                float m2 = __shfl_down_sync(0xffffffffu, mm, o);
                float l2 = __shfl_down_sync(0xffffffffu, lll, o);
                float M = fmaxf(mm, m2);
                lll = lll * expf(mm - M) + l2 * expf(m2 - M);
                mm = M;
            }
            if (lane == 0) sredw[0] = mm + logf(lll);
        }
        __syncthreads();
        float lse = sredw[0];
        int i = b * NTHR + tid;
        if (i < VOCAB) out[i] -= lse;
    }
}

// ---------------- launch ----------------
extern "C" void kernel_launch(void* const* d_in, const int* in_sizes, int n_in,
                              void* d_out, int out_size) {
    const float* attn  = (const float*)d_in[0];
    const float* x     = (const float*)d_in[1];
    const float* h     = (const float*)d_in[2];
    const float* c     = (const float*)d_in[3];
    const float* W_ih  = (const float*)d_in[4];
    const float* W_hh  = (const float*)d_in[5];
    const float* b_ih  = (const float*)d_in[6];
    const float* b_hh  = (const float*)d_in[7];
    const float* fc1_w = (const float*)d_in[8];
    const float* fc1_b = (const float*)d_in[9];
    const float* fc2_w = (const float*)d_in[10];
    const float* fc2_b = (const float*)d_in[11];
    float* out = (float*)d_out;

    fused_all<<<NBLK, NTHR>>>(attn, x, h, c, W_ih, W_hh, b_ih, b_hh,
                              fc1_w, fc1_b, fc2_w, fc2_b, out);
}